// round 14
// baseline (speedup 1.0000x reference)
#include <cuda_runtime.h>
#include <cstdint>

static constexpr int B = 4, S = 2048, D = 1024, H = 16, HD = 64;
static constexpr int M = B * S;  // 8192

__device__ float g_q[(size_t)B * H * S * HD];   // tf32-rounded at GEMM epilogue
__device__ float g_k[(size_t)B * H * S * HD];   // tf32-rounded
__device__ float g_v[(size_t)B * H * S * HD];   // [bh][hd][S] transposed, tf32-rounded
__device__ float g_att[(size_t)B * S * D];      // tf32-rounded by flash epilogue
__device__ float g_xr[(size_t)M * D];           // tf32-rounded x
__device__ float g_wr[(size_t)4 * D * D];       // tf32-rounded Wq,Wk,Wv,Wo
__device__ unsigned char g_qmask[B * S];
__device__ int g_sig;

// ---------------- helpers ----------------
__device__ __forceinline__ unsigned f2tf(float x) {
    unsigned u;
    asm("cvt.rna.tf32.f32 %0, %1;" : "=r"(u) : "f"(x));
    return u;
}
__device__ __forceinline__ float f2tff(float x) { return __uint_as_float(f2tf(x)); }

__device__ __forceinline__ void mma_tf32(float& c0, float& c1, float& c2, float& c3,
                                         unsigned a0, unsigned a1, unsigned a2, unsigned a3,
                                         unsigned b0, unsigned b1) {
    asm("mma.sync.aligned.m16n8k8.row.col.f32.tf32.tf32.f32 "
        "{%0,%1,%2,%3}, {%4,%5,%6,%7}, {%8,%9}, {%0,%1,%2,%3};"
        : "+f"(c0), "+f"(c1), "+f"(c2), "+f"(c3)
        : "r"(a0), "r"(a1), "r"(a2), "r"(a3), "r"(b0), "r"(b1));
}

__device__ __forceinline__ void ldsm4(unsigned& r0, unsigned& r1, unsigned& r2, unsigned& r3,
                                      const float* p) {
    unsigned a = (unsigned)__cvta_generic_to_shared(p);
    asm volatile("ldmatrix.sync.aligned.m8n8.x4.shared.b16 {%0,%1,%2,%3}, [%4];"
                 : "=r"(r0), "=r"(r1), "=r"(r2), "=r"(r3) : "r"(a));
}

__device__ __forceinline__ void cp16(const float* smem_dst, const float* gsrc) {
    unsigned d = (unsigned)__cvta_generic_to_shared(smem_dst);
    asm volatile("cp.async.cg.shared.global [%0], [%1], 16;" :: "r"(d), "l"(gsrc));
}
__device__ __forceinline__ void cp_commit() {
    asm volatile("cp.async.commit_group;");
}
__device__ __forceinline__ void cp_wait1() {
    asm volatile("cp.async.wait_group 1;");
}

// ---------------- tf32 pre-rounding pass ----------------
__global__ void k_round(const float* __restrict__ in, float* __restrict__ out, int n4) {
    int i = blockIdx.x * blockDim.x + threadIdx.x;
    if (i >= n4) return;
    float4 v = ((const float4*)in)[i];
    v.x = f2tff(v.x); v.y = f2tff(v.y); v.z = f2tff(v.z); v.w = f2tff(v.w);
    ((float4*)out)[i] = v;
}

// ---------------- mask dtype canonicalization ----------------
__global__ void k_init_sig() { g_sig = 0; }

__global__ void k_detect(const unsigned char* __restrict__ p) {
    int q = blockIdx.x * blockDim.x + threadIdx.x;
    if (q < B * S) {
        if (p[q] != 0) atomicOr(&g_sig, 1 << (q & 3));
    }
}

__global__ void k_convert(const void* __restrict__ p) {
    int q = blockIdx.x * blockDim.x + threadIdx.x;
    if (q >= B * S) return;
    int sig = g_sig;
    bool m;
    if (sig & 0x2)      m = ((const unsigned char*)p)[q] != 0;
    else if (sig & 0x4) m = ((const float*)p)[q] != 0.0f;
    else                m = ((const int*)p)[q] != 0;
    g_qmask[q] = m ? 1 : 0;
}

// ---------------- tf32 SGEMM: 3-stage cp.async pipeline (pre-rounded inputs) ----------------
// C[M,1024] = A[M,1024] @ W[1024,1024] + bias
// LAYOUT 0: row-major [M,N] (raw fp32); 1: scatter [B,H,S,HD] (tf32-rounded);
// 2: transposed [bh][hd][S] (tf32-rounded)
template <int LAYOUT>
__global__ void __launch_bounds__(256, 2) k_gemm(const float* __restrict__ A,
                                                 const float* __restrict__ W,
                                                 const float* __restrict__ bias,
                                                 float* __restrict__ C)
{
    constexpr int N = 1024, K = 1024;
    constexpr int AS_STRIDE = 128 * 20;
    constexpr int BS_STRIDE = 16 * 136;
    extern __shared__ float sh[];
    float* As = sh;
    float* Bs = sh + 3 * AS_STRIDE;

    const int t = threadIdx.x, lane = t & 31, wid = t >> 5;
    const int g = lane >> 2, q = lane & 3;
    const int wm = (wid & 3) * 32;
    const int wn = (wid >> 2) * 64;
    const int bx = blockIdx.x, by = blockIdx.y;

    float c[2][8][4];
    #pragma unroll
    for (int mf = 0; mf < 2; ++mf)
        #pragma unroll
        for (int nf = 0; nf < 8; ++nf)
            #pragma unroll
            for (int i = 0; i < 4; ++i) c[mf][nf][i] = 0.f;

    const int aRow0 = t >> 2, aK0 = (t & 3) * 4;
    const int aRow1 = aRow0 + 64;
    const int bK0 = t >> 5,  bC0 = (t & 31) * 4;
    const int bK1 = bK0 + 8;

    const float* Abase = A + (size_t)(by * 128) * K;
    const float* Wbase = W + bx * 128;

    auto fill = [&](int s, int kb) {
        float* As_s = As + s * AS_STRIDE;
        float* Bs_s = Bs + s * BS_STRIDE;
        cp16(As_s + aRow0 * 20 + aK0, Abase + (size_t)aRow0 * K + kb + aK0);
        cp16(As_s + aRow1 * 20 + aK0, Abase + (size_t)aRow1 * K + kb + aK0);
        cp16(Bs_s + bK0 * 136 + bC0, Wbase + (size_t)(kb + bK0) * N + bC0);
        cp16(Bs_s + bK1 * 136 + bC0, Wbase + (size_t)(kb + bK1) * N + bC0);
    };

    fill(0, 0);  cp_commit();
    fill(1, 16); cp_commit();

    constexpr int NT = K / 16;  // 64
    int cur = 0;
    for (int kt = 0; kt < NT; ++kt) {
        cp_wait1();
        __syncthreads();
        if (kt + 2 < NT) fill((kt + 2) % 3, (kt + 2) * 16);
        cp_commit();

        const float* As_c = As + cur * AS_STRIDE;
        const float* Bs_c = Bs + cur * BS_STRIDE;
        cur = (cur + 1 == 3) ? 0 : cur + 1;

        #pragma unroll
        for (int ks = 0; ks < 2; ++ks) {
            const int k0 = ks * 8;
            unsigned a[2][4];
            #pragma unroll
            for (int mf = 0; mf < 2; ++mf) {
                int r = wm + mf * 16 + g;
                a[mf][0] = __float_as_uint(As_c[r * 20 + k0 + q]);
                a[mf][1] = __float_as_uint(As_c[(r + 8) * 20 + k0 + q]);
                a[mf][2] = __float_as_uint(As_c[r * 20 + k0 + q + 4]);
                a[mf][3] = __float_as_uint(As_c[(r + 8) * 20 + k0 + q + 4]);
            }
            #pragma unroll
            for (int nf = 0; nf < 8; ++nf) {
                int col = wn + nf * 8 + g;
                unsigned b0 = __float_as_uint(Bs_c[(k0 + q) * 136 + col]);
                unsigned b1 = __float_as_uint(Bs_c[(k0 + q + 4) * 136 + col]);
                #pragma unroll
                for (int mf = 0; mf < 2; ++mf)
                    mma_tf32(c[mf][nf][0], c[mf][nf][1], c[mf][nf][2], c[mf][nf][3],
                             a[mf][0], a[mf][1], a[mf][2], a[mf][3], b0, b1);
            }
        }
    }

    // epilogue: bias + store
    #pragma unroll
    for (int mf = 0; mf < 2; ++mf) {
        #pragma unroll
        for (int half = 0; half < 2; ++half) {
            int gm = by * 128 + wm + mf * 16 + g + half * 8;
            #pragma unroll
            for (int nf = 0; nf < 8; ++nf) {
                int gn = bx * 128 + wn + nf * 8 + 2 * q;
                float v0 = c[mf][nf][half * 2 + 0] + bias[gn];
                float v1 = c[mf][nf][half * 2 + 1] + bias[gn + 1];
                if (LAYOUT == 0) {
                    *(float2*)&C[(size_t)gm * N + gn] = make_float2(v0, v1);
                } else if (LAYOUT == 1) {
                    int bb_ = gm >> 11, ss = gm & (S - 1);
                    int hh = gn >> 6, dd = gn & 63;
                    *(float2*)&C[(((size_t)(bb_ * H + hh)) * S + ss) * HD + dd] =
                        make_float2(f2tff(v0), f2tff(v1));
                } else {
                    int bb_ = gm >> 11, ss = gm & (S - 1);
                    int hh = gn >> 6, dd = gn & 63;
                    float* base = C + ((size_t)(bb_ * H + hh) * HD + dd) * S + ss;
                    base[0] = f2tff(v0);
                    base[S] = f2tff(v1);
                }
            }
        }
    }
}

// ---------------- fused flash attention (reg-Q, double-buffered cp.async K/V) ----------------
// grid (H, B*(S/128)), 256 threads (8 warps); warp w owns query rows [16w,16w+16)
// smem: stage s in [s*8704, s*8704+8704): Ks [64][68] + Vt [64][68]; Ps at 17408.
__global__ void __launch_bounds__(256, 2) k_flash(const float* __restrict__ mod)
{
    extern __shared__ float sh[];
    float* Ps = sh + 17408;            // [128][68]

    const int t = threadIdx.x, lane = t & 31, w = t >> 5;
    const int g = lane >> 2, q = lane & 3;
    const int h = blockIdx.x;
    const int by = blockIdx.y;
    const int b = by >> 4, qt = by & 15;
    const int bh = b * H + h;
    const int rowA = (lane & 7) + ((lane & 8) ? 8 : 0);   // a-frag ldsm rows
    const int colA = (lane & 16) ? 4 : 0;
    const int rowK = (lane & 7) + ((lane & 16) ? 8 : 0);  // b-frag ldsm rows
    const int colK = (lane & 8) ? 4 : 0;

    const float* qg  = g_q + ((size_t)bh * S + qt * 128) * HD;
    const float* kg  = g_k + (size_t)bh * S * HD;
    const float* vtg = g_v + (size_t)bh * HD * S;   // [hd][S]

    // stage Q (pre-rounded) into sh[0..8704), extract fragments to registers
    #pragma unroll
    for (int i = 0; i < 8; ++i) {
        int idx = t + i * 256;
        int r = idx >> 4, cc = (idx & 15) * 4;
        *(float4*)&sh[r * 68 + cc] = *(const float4*)(qg + r * 64 + cc);
    }
    __syncthreads();
    unsigned qf[8][4];
    #pragma unroll
    for (int kk = 0; kk < 8; ++kk)
        ldsm4(qf[kk][0], qf[kk][1], qf[kk][2], qf[kk][3],
              &sh[(w * 16 + rowA) * 68 + kk * 8 + colA]);
    __syncthreads();   // all warps done reading Q before stage 0 overwrites it

    auto fillKV = [&](int stage, int nt) {
        float* Ks_s = sh + stage * 8704;
        float* Vt_s = Ks_s + 4352;
        #pragma unroll
        for (int i = 0; i < 4; ++i) {
            int idx = t + i * 256;
            int r = idx >> 4, cc = (idx & 15) * 4;
            cp16(Ks_s + r * 68 + cc, kg + (size_t)(nt * 64 + r) * 64 + cc);
            cp16(Vt_s + r * 68 + cc, vtg + (size_t)r * S + nt * 64 + cc);
        }
    };
    fillKV(0, 0); cp_commit();
    fillKV(1, 1); cp_commit();

    const int r0 = w * 16 + g;
    const bool qm0 = g_qmask[b * S + qt * 128 + r0] != 0;
    const bool qm1 = g_qmask[b * S + qt * 128 + r0 + 8] != 0;
    const float* m0p = mod + ((size_t)b * S + qt * 128 + r0) * S;
    const float* m1p = m0p + (size_t)8 * S;

    float o[8][4];
    #pragma unroll
    for (int nf = 0; nf < 8; ++nf)
        #pragma unroll
        for (int i = 0; i < 4; ++i) o[nf][i] = 0.f;
    float mr0 = -1e30f, mr1 = -1e30f, l0 = 0.f, l1 = 0.f;

    constexpr int NT = S / 64;  // 32
    for (int nt = 0; nt < NT; ++nt) {
        cp_wait1();          // stage nt resident (nt+1 may be in flight)
        __syncthreads();
        const float* Ks = sh + (nt & 1) * 8704;
        const float* Vt = Ks + 4352;

        // ---- S = Q @ K^T (Q from registers) ----
        float s[8][4];
        #pragma unroll
        for (int nf = 0; nf < 8; ++nf)
            #pragma unroll
            for (int i = 0; i < 4; ++i) s[nf][i] = 0.f;

        #pragma unroll
        for (int kk = 0; kk < 8; ++kk) {
            #pragma unroll
            for (int nf2 = 0; nf2 < 4; ++nf2) {
                unsigned b0, b1, b2, b3;
                ldsm4(b0, b1, b2, b3, &Ks[(nf2 * 16 + rowK) * 68 + kk * 8 + colK]);
                mma_tf32(s[2 * nf2][0], s[2 * nf2][1], s[2 * nf2][2], s[2 * nf2][3],
                         qf[kk][0], qf[kk][1], qf[kk][2], qf[kk][3], b0, b1);
                mma_tf32(s[2 * nf2 + 1][0], s[2 * nf2 + 1][1], s[2 * nf2 + 1][2],
                         s[2 * nf2 + 1][3],
                         qf[kk][0], qf[kk][1], qf[kk][2], qf[kk][3], b2, b3);
            }
        }

        // ---- modifier * scale, mask, online softmax ----
        float mx0 = -1e30f, mx1 = -1e30f;
        #pragma unroll
        for (int nf = 0; nf < 8; ++nf) {
            float2 md0 = *(const float2*)(m0p + nt * 64 + nf * 8 + 2 * q);
            float2 md1 = *(const float2*)(m1p + nt * 64 + nf * 8 + 2 * q);
            s[nf][0] = qm0 ? -1e10f : s[nf][0] * 0.125f * md0.x;
            s[nf][1] = qm0 ? -1e10f : s[nf][1] * 0.125f * md0.y;
            s[nf][2] = qm1 ? -1e10f : s[nf][2] * 0.125f * md1.x;
            s[nf][3] = qm1 ? -1e10f : s[nf][3] * 0.125f * md1.y;
            mx0 = fmaxf(mx0, fmaxf(s[nf][0], s[nf][1]));
            mx1 = fmaxf(mx1, fmaxf(s[nf][2], s[nf][3]));
        }
        mx0 = fmaxf(mx0, __shfl_xor_sync(0xffffffffu, mx0, 1));
        mx0 = fmaxf(mx0, __shfl_xor_sync(0xffffffffu, mx0, 2));
        mx1 = fmaxf(mx1, __shfl_xor_sync(0xffffffffu, mx1, 1));
        mx1 = fmaxf(mx1, __shfl_xor_sync(0xffffffffu, mx1, 2));

        float mn0 = fmaxf(mr0, mx0), mn1 = fmaxf(mr1, mx1);
        float co0 = __expf(mr0 - mn0), co1 = __expf(mr1 - mn1);
        float rs0 = 0.f, rs1 = 0.f;
        #pragma unroll
        for (int nf = 0; nf < 8; ++nf) {
            float p0 = __expf(s[nf][0] - mn0);
            float p1 = __expf(s[nf][1] - mn0);
            float p2 = __expf(s[nf][2] - mn1);
            float p3 = __expf(s[nf][3] - mn1);
            rs0 += p0 + p1; rs1 += p2 + p3;
            *(float2*)&Ps[r0 * 68 + nf * 8 + 2 * q]       = make_float2(f2tff(p0), f2tff(p1));
            *(float2*)&Ps[(r0 + 8) * 68 + nf * 8 + 2 * q] = make_float2(f2tff(p2), f2tff(p3));
        }
        rs0 += __shfl_xor_sync(0xffffffffu, rs0, 1);
        rs0 += __shfl_xor_sync(0xffffffffu, rs0, 2);
        rs1 += __shfl_xor_sync(0xffffffffu, rs1, 1);
        rs1 += __shfl_xor_sync(0xffffffffu, rs1, 2);
        l0 = l0 * co0 + rs0;
        l1 = l1 * co1 + rs1;
        mr0 = mn0; mr1 = mn1;
        #pragma unroll
        for (int nf = 0; nf < 8; ++nf) {
            o[nf][0] *= co0; o[nf][1] *= co0;
            o[nf][2] *= co1; o[nf][3] *= co1;
        }
        __syncwarp();   // Ps rows of this warp written only by this warp

        // ---- O += P @ V ----
        #pragma unroll
        for (int kk = 0; kk < 8; ++kk) {
            unsigned a0, a1, a2, a3;
            ldsm4(a0, a1, a2, a3, &Ps[(w * 16 + rowA) * 68 + kk * 8 + colA]);
            #pragma unroll
            for (int nf2 = 0; nf2 < 4; ++nf2) {
                unsigned b0, b1, b2, b3;
                ldsm4(b0, b1, b2, b3, &Vt[(nf2 * 16 + rowK) * 68 + kk * 8 + colK]);
                mma_tf32(o[2 * nf2][0], o[2 * nf2][1], o[2 * nf2][2], o[2 * nf2][3],
                         a0, a1, a2, a3, b0, b1);
                mma_tf32(o[2 * nf2 + 1][0], o[2 * nf2 + 1][1], o[2 * nf2 + 1][2],
                         o[2 * nf2 + 1][3], a0, a1, a2, a3, b2, b3);
            }
        }

        __syncthreads();   // all warps done reading stage nt before refilling it
        if (nt + 2 < NT) fillKV(nt & 1, nt + 2);
        cp_commit();
    }

    // normalize, write [B,S,D] (tf32-rounded: feeds the output-projection GEMM)
    float i0 = 1.0f / l0, i1 = 1.0f / l1;
    float* ob = g_att + ((size_t)b * S + qt * 128) * D + h * 64;
    #pragma unroll
    for (int nf = 0; nf < 8; ++nf) {
        *(float2*)&ob[(size_t)r0 * D + nf * 8 + 2 * q] =
            make_float2(f2tff(o[nf][0] * i0), f2tff(o[nf][1] * i0));
        *(float2*)&ob[(size_t)(r0 + 8) * D + nf * 8 + 2 * q] =
            make_float2(f2tff(o[nf][2] * i1), f2tff(o[nf][3] * i1));
    }
}

// ---------------- launch ----------------
extern "C" void kernel_launch(void* const* d_in, const int* in_sizes, int n_in,
                              void* d_out, int out_size)
{
    const float* x   = (const float*)d_in[0];
    const void*  kpm = d_in[1];
    const float* mod = (const float*)d_in[2];
    const float* Wq  = (const float*)d_in[3];
    const float* bq  = (const float*)d_in[4];
    const float* Wk  = (const float*)d_in[5];
    const float* bk  = (const float*)d_in[6];
    const float* Wv  = (const float*)d_in[7];
    const float* bv  = (const float*)d_in[8];
    const float* Wo  = (const float*)d_in[9];
    const float* bo  = (const float*)d_in[10];
    float* out = (float*)d_out;

    float *qp, *kp, *vp, *ap, *xr, *wr;
    cudaGetSymbolAddress((void**)&qp, g_q);
    cudaGetSymbolAddress((void**)&kp, g_k);
    cudaGetSymbolAddress((void**)&vp, g_v);
    cudaGetSymbolAddress((void**)&ap, g_att);
    cudaGetSymbolAddress((void**)&xr, g_xr);
    cudaGetSymbolAddress((void**)&wr, g_wr);

    k_init_sig<<<1, 1>>>();
    k_detect<<<(B * S + 255) / 256, 256>>>((const unsigned char*)kpm);
    k_convert<<<(B * S + 255) / 256, 256>>>(kpm);

    const int n4x = M * D / 4, n4w = D * D / 4;
    k_round<<<(n4x + 255) / 256, 256>>>(x,  xr, n4x);
    k_round<<<(n4w + 255) / 256, 256>>>(Wq, wr + 0 * (size_t)D * D, n4w);
    k_round<<<(n4w + 255) / 256, 256>>>(Wk, wr + 1 * (size_t)D * D, n4w);
    k_round<<<(n4w + 255) / 256, 256>>>(Wv, wr + 2 * (size_t)D * D, n4w);
    k_round<<<(n4w + 255) / 256, 256>>>(Wo, wr + 3 * (size_t)D * D, n4w);

    constexpr int GSMEM = 3 * (128 * 20 + 16 * 136) * 4;  // 56832 B
    cudaFuncSetAttribute(k_gemm<0>, cudaFuncAttributeMaxDynamicSharedMemorySize, GSMEM);
    cudaFuncSetAttribute(k_gemm<1>, cudaFuncAttributeMaxDynamicSharedMemorySize, GSMEM);
    cudaFuncSetAttribute(k_gemm<2>, cudaFuncAttributeMaxDynamicSharedMemorySize, GSMEM);

    dim3 gg(D / 128, M / 128);
    k_gemm<1><<<gg, 256, GSMEM>>>(xr, wr + 0 * (size_t)D * D, bq, qp);
    k_gemm<1><<<gg, 256, GSMEM>>>(xr, wr + 1 * (size_t)D * D, bk, kp);
    k_gemm<2><<<gg, 256, GSMEM>>>(xr, wr + 2 * (size_t)D * D, bv, vp);

    constexpr int SMEM = (2 * 8704 + 128 * 68) * 4;  // 104448 B
    cudaFuncSetAttribute(k_flash, cudaFuncAttributeMaxDynamicSharedMemorySize, SMEM);
    k_flash<<<dim3(H, B * (S / 128)), 256, SMEM>>>(mod);

    k_gemm<0><<<gg, 256, GSMEM>>>(ap, wr + 3 * (size_t)D * D, bo, out);
}

// round 17
// speedup vs baseline: 1.2761x; 1.2761x over previous
#include <cuda_runtime.h>
#include <cuda_fp16.h>
#include <cstdint>

static constexpr int B = 4, S = 2048, D = 1024, H = 16, HD = 64;
static constexpr int M = B * S;  // 8192

__device__ __half g_q[(size_t)B * H * S * HD];   // [B,H,S,HD] fp16
__device__ __half g_k[(size_t)B * H * S * HD];   // [B,H,S,HD] fp16
__device__ __half g_v[(size_t)B * H * S * HD];   // [bh][hd][S] transposed fp16
__device__ float  g_att[(size_t)B * S * D];      // tf32-rounded by flash epilogue
__device__ float  g_xr[(size_t)M * D];           // tf32-rounded x
__device__ float  g_wr[(size_t)4 * D * D];       // tf32-rounded Wq,Wk,Wv,Wo
__device__ unsigned char g_qmask[B * S];
__device__ int g_sig;

// ---------------- helpers ----------------
__device__ __forceinline__ unsigned f2tf(float x) {
    unsigned u;
    asm("cvt.rna.tf32.f32 %0, %1;" : "=r"(u) : "f"(x));
    return u;
}
__device__ __forceinline__ float f2tff(float x) { return __uint_as_float(f2tf(x)); }

__device__ __forceinline__ void mma_tf32(float& c0, float& c1, float& c2, float& c3,
                                         unsigned a0, unsigned a1, unsigned a2, unsigned a3,
                                         unsigned b0, unsigned b1) {
    asm("mma.sync.aligned.m16n8k8.row.col.f32.tf32.tf32.f32 "
        "{%0,%1,%2,%3}, {%4,%5,%6,%7}, {%8,%9}, {%0,%1,%2,%3};"
        : "+f"(c0), "+f"(c1), "+f"(c2), "+f"(c3)
        : "r"(a0), "r"(a1), "r"(a2), "r"(a3), "r"(b0), "r"(b1));
}

__device__ __forceinline__ void mma_f16(float& c0, float& c1, float& c2, float& c3,
                                        unsigned a0, unsigned a1, unsigned a2, unsigned a3,
                                        unsigned b0, unsigned b1) {
    asm("mma.sync.aligned.m16n8k16.row.col.f32.f16.f16.f32 "
        "{%0,%1,%2,%3}, {%4,%5,%6,%7}, {%8,%9}, {%0,%1,%2,%3};"
        : "+f"(c0), "+f"(c1), "+f"(c2), "+f"(c3)
        : "r"(a0), "r"(a1), "r"(a2), "r"(a3), "r"(b0), "r"(b1));
}

__device__ __forceinline__ void ldsm4(unsigned& r0, unsigned& r1, unsigned& r2, unsigned& r3,
                                      const void* p) {
    unsigned a = (unsigned)__cvta_generic_to_shared(p);
    asm volatile("ldmatrix.sync.aligned.m8n8.x4.shared.b16 {%0,%1,%2,%3}, [%4];"
                 : "=r"(r0), "=r"(r1), "=r"(r2), "=r"(r3) : "r"(a));
}

__device__ __forceinline__ void cp16(const float* smem_dst, const float* gsrc) {
    unsigned d = (unsigned)__cvta_generic_to_shared(smem_dst);
    asm volatile("cp.async.cg.shared.global [%0], [%1], 16;" :: "r"(d), "l"(gsrc));
}
__device__ __forceinline__ void cp_commit() { asm volatile("cp.async.commit_group;"); }
__device__ __forceinline__ void cp_wait1()  { asm volatile("cp.async.wait_group 1;"); }

// ---------------- tf32 pre-rounding pass ----------------
__global__ void k_round(const float* __restrict__ in, float* __restrict__ out, int n4) {
    int i = blockIdx.x * blockDim.x + threadIdx.x;
    if (i >= n4) return;
    float4 v = ((const float4*)in)[i];
    v.x = f2tff(v.x); v.y = f2tff(v.y); v.z = f2tff(v.z); v.w = f2tff(v.w);
    ((float4*)out)[i] = v;
}

// ---------------- mask dtype canonicalization ----------------
__global__ void k_init_sig() { g_sig = 0; }

__global__ void k_detect(const unsigned char* __restrict__ p) {
    int q = blockIdx.x * blockDim.x + threadIdx.x;
    if (q < B * S) {
        if (p[q] != 0) atomicOr(&g_sig, 1 << (q & 3));
    }
}

__global__ void k_convert(const void* __restrict__ p) {
    int q = blockIdx.x * blockDim.x + threadIdx.x;
    if (q >= B * S) return;
    int sig = g_sig;
    bool m;
    if (sig & 0x2)      m = ((const unsigned char*)p)[q] != 0;
    else if (sig & 0x4) m = ((const float*)p)[q] != 0.0f;
    else                m = ((const int*)p)[q] != 0;
    g_qmask[q] = m ? 1 : 0;
}

// ---------------- tf32 SGEMM: 3-stage cp.async pipeline (R13, proven) ----------------
// C[M,1024] = A[M,1024] @ W[1024,1024] + bias
// LAYOUT 0: fp32 row-major [M,N]; 1: fp16 scatter [B,H,S,HD]; 2: fp16 transposed [bh][hd][S]
template <int LAYOUT>
__global__ void __launch_bounds__(256, 2) k_gemm(const float* __restrict__ A,
                                                 const float* __restrict__ W,
                                                 const float* __restrict__ bias,
                                                 void* __restrict__ Cv)
{
    constexpr int N = 1024, K = 1024;
    constexpr int AS_STRIDE = 128 * 20;
    constexpr int BS_STRIDE = 16 * 136;
    extern __shared__ float sh[];
    float* As = sh;
    float* Bs = sh + 3 * AS_STRIDE;

    const int t = threadIdx.x, lane = t & 31, wid = t >> 5;
    const int g = lane >> 2, q = lane & 3;
    const int wm = (wid & 3) * 32;
    const int wn = (wid >> 2) * 64;
    const int bx = blockIdx.x, by = blockIdx.y;

    float c[2][8][4];
    #pragma unroll
    for (int mf = 0; mf < 2; ++mf)
        #pragma unroll
        for (int nf = 0; nf < 8; ++nf)
            #pragma unroll
            for (int i = 0; i < 4; ++i) c[mf][nf][i] = 0.f;

    const int aRow0 = t >> 2, aK0 = (t & 3) * 4;
    const int aRow1 = aRow0 + 64;
    const int bK0 = t >> 5,  bC0 = (t & 31) * 4;
    const int bK1 = bK0 + 8;

    const float* Abase = A + (size_t)(by * 128) * K;
    const float* Wbase = W + bx * 128;

    auto fill = [&](int s, int kb) {
        float* As_s = As + s * AS_STRIDE;
        float* Bs_s = Bs + s * BS_STRIDE;
        cp16(As_s + aRow0 * 20 + aK0, Abase + (size_t)aRow0 * K + kb + aK0);
        cp16(As_s + aRow1 * 20 + aK0, Abase + (size_t)aRow1 * K + kb + aK0);
        cp16(Bs_s + bK0 * 136 + bC0, Wbase + (size_t)(kb + bK0) * N + bC0);
        cp16(Bs_s + bK1 * 136 + bC0, Wbase + (size_t)(kb + bK1) * N + bC0);
    };

    fill(0, 0);  cp_commit();
    fill(1, 16); cp_commit();

    constexpr int NT = K / 16;  // 64
    int cur = 0;
    for (int kt = 0; kt < NT; ++kt) {
        cp_wait1();
        __syncthreads();
        if (kt + 2 < NT) fill((kt + 2) % 3, (kt + 2) * 16);
        cp_commit();

        const float* As_c = As + cur * AS_STRIDE;
        const float* Bs_c = Bs + cur * BS_STRIDE;
        cur = (cur + 1 == 3) ? 0 : cur + 1;

        #pragma unroll
        for (int ks = 0; ks < 2; ++ks) {
            const int k0 = ks * 8;
            unsigned a[2][4];
            #pragma unroll
            for (int mf = 0; mf < 2; ++mf) {
                int r = wm + mf * 16 + g;
                a[mf][0] = __float_as_uint(As_c[r * 20 + k0 + q]);
                a[mf][1] = __float_as_uint(As_c[(r + 8) * 20 + k0 + q]);
                a[mf][2] = __float_as_uint(As_c[r * 20 + k0 + q + 4]);
                a[mf][3] = __float_as_uint(As_c[(r + 8) * 20 + k0 + q + 4]);
            }
            #pragma unroll
            for (int nf = 0; nf < 8; ++nf) {
                int col = wn + nf * 8 + g;
                unsigned b0 = __float_as_uint(Bs_c[(k0 + q) * 136 + col]);
                unsigned b1 = __float_as_uint(Bs_c[(k0 + q + 4) * 136 + col]);
                #pragma unroll
                for (int mf = 0; mf < 2; ++mf)
                    mma_tf32(c[mf][nf][0], c[mf][nf][1], c[mf][nf][2], c[mf][nf][3],
                             a[mf][0], a[mf][1], a[mf][2], a[mf][3], b0, b1);
            }
        }
    }

    // epilogue: bias + store
    #pragma unroll
    for (int mf = 0; mf < 2; ++mf) {
        #pragma unroll
        for (int half = 0; half < 2; ++half) {
            int gm = by * 128 + wm + mf * 16 + g + half * 8;
            #pragma unroll
            for (int nf = 0; nf < 8; ++nf) {
                int gn = bx * 128 + wn + nf * 8 + 2 * q;
                float v0 = c[mf][nf][half * 2 + 0] + bias[gn];
                float v1 = c[mf][nf][half * 2 + 1] + bias[gn + 1];
                if (LAYOUT == 0) {
                    float* C = (float*)Cv;
                    *(float2*)&C[(size_t)gm * N + gn] = make_float2(v0, v1);
                } else if (LAYOUT == 1) {
                    __half* C = (__half*)Cv;
                    int bb_ = gm >> 11, ss = gm & (S - 1);
                    int hh = gn >> 6, dd = gn & 63;
                    *(__half2*)&C[(((size_t)(bb_ * H + hh)) * S + ss) * HD + dd] =
                        __floats2half2_rn(v0, v1);
                } else {
                    __half* C = (__half*)Cv;
                    int bb_ = gm >> 11, ss = gm & (S - 1);
                    int hh = gn >> 6, dd = gn & 63;
                    __half* base = C + ((size_t)(bb_ * H + hh) * HD + dd) * S + ss;
                    base[0] = __float2half_rn(v0);
                    base[S] = __float2half_rn(v1);
                }
            }
        }
    }
}

// ---------------- fused flash attention (fp16 m16n8k16) ----------------
// grid (H, B*(S/128)), 256 threads (8 warps); warp w owns query rows [16w,16w+16)
// smem (halves, pitch 72): Qs[128][72], Ks[64][72], Vt[64][72], Ps[128][72]
__global__ void __launch_bounds__(256, 2) k_flash(const float* __restrict__ mod)
{
    extern __shared__ __half shh[];
    __half* Qs = shh;                  // [128][72]
    __half* Ks = Qs + 128 * 72;        // [64][72]  rows=key, cols=hd
    __half* Vt = Ks + 64 * 72;         // [64][72]  rows=hd,  cols=key
    __half* Ps = Vt + 64 * 72;         // [128][72]

    const int t = threadIdx.x, lane = t & 31, w = t >> 5;
    const int g = lane >> 2, q = lane & 3;
    const int h = blockIdx.x;
    const int by = blockIdx.y;
    const int b = by >> 4, qt = by & 15;
    const int bh = b * H + h;
    // a-frag ldsm: rows (lane&7)+(lane&8?8), k-half (lane&16?8)
    const int rowA = (lane & 7) + ((lane & 8) ? 8 : 0);
    const int colA = (lane & 16) ? 8 : 0;
    // b-frag ldsm (B stored [n][k]): rows (lane&7)+(lane&16?8), k-half (lane&8?8)
    const int rowB = (lane & 7) + ((lane & 16) ? 8 : 0);
    const int colB = (lane & 8) ? 8 : 0;

    const __half* qg  = g_q + ((size_t)bh * S + qt * 128) * HD;
    const __half* kg  = g_k + (size_t)bh * S * HD;
    const __half* vtg = g_v + (size_t)bh * HD * S;   // [hd][S]

    // Q fill: 128x64 halves = 1024 uint4; 4 per thread
    #pragma unroll
    for (int i = 0; i < 4; ++i) {
        int idx = t + i * 256;
        int r = idx >> 3, c8 = (idx & 7) * 8;
        *(uint4*)&Qs[r * 72 + c8] = *(const uint4*)(qg + r * 64 + c8);
    }

    const int r0 = w * 16 + g;
    const bool qm0 = g_qmask[b * S + qt * 128 + r0] != 0;
    const bool qm1 = g_qmask[b * S + qt * 128 + r0 + 8] != 0;
    const float* m0p = mod + ((size_t)b * S + qt * 128 + r0) * S;
    const float* m1p = m0p + (size_t)8 * S;

    float o[8][4];
    #pragma unroll
    for (int nf = 0; nf < 8; ++nf)
        #pragma unroll
        for (int i = 0; i < 4; ++i) o[nf][i] = 0.f;
    float mr0 = -1e30f, mr1 = -1e30f, l0 = 0.f, l1 = 0.f;

    __syncthreads();

    for (int nt = 0; nt < S / 64; ++nt) {
        if (nt) __syncthreads();
        // K [key][hd] and Vt [hd][key] fills: 64x64 halves = 512 uint4 each; 2 per thread
        #pragma unroll
        for (int i = 0; i < 2; ++i) {
            int idx = t + i * 256;
            int r = idx >> 3, c8 = (idx & 7) * 8;
            *(uint4*)&Ks[r * 72 + c8] = *(const uint4*)(kg + (size_t)(nt * 64 + r) * 64 + c8);
            *(uint4*)&Vt[r * 72 + c8] = *(const uint4*)(vtg + (size_t)r * S + nt * 64 + c8);
        }
        __syncthreads();

        // ---- S = Q @ K^T ----
        float s[8][4];
        #pragma unroll
        for (int nf = 0; nf < 8; ++nf)
            #pragma unroll
            for (int i = 0; i < 4; ++i) s[nf][i] = 0.f;

        #pragma unroll
        for (int kc = 0; kc < 4; ++kc) {
            unsigned a0, a1, a2, a3;
            ldsm4(a0, a1, a2, a3, &Qs[(w * 16 + rowA) * 72 + kc * 16 + colA]);
            #pragma unroll
            for (int nb = 0; nb < 4; ++nb) {
                unsigned b0, b1, b2, b3;
                ldsm4(b0, b1, b2, b3, &Ks[(nb * 16 + rowB) * 72 + kc * 16 + colB]);
                mma_f16(s[2 * nb][0], s[2 * nb][1], s[2 * nb][2], s[2 * nb][3],
                        a0, a1, a2, a3, b0, b1);
                mma_f16(s[2 * nb + 1][0], s[2 * nb + 1][1], s[2 * nb + 1][2],
                        s[2 * nb + 1][3], a0, a1, a2, a3, b2, b3);
            }
        }

        // ---- modifier * scale, mask, online softmax ----
        float mx0 = -1e30f, mx1 = -1e30f;
        #pragma unroll
        for (int nf = 0; nf < 8; ++nf) {
            float2 md0 = *(const float2*)(m0p + nt * 64 + nf * 8 + 2 * q);
            float2 md1 = *(const float2*)(m1p + nt * 64 + nf * 8 + 2 * q);
            s[nf][0] = qm0 ? -1e10f : s[nf][0] * 0.125f * md0.x;
            s[nf][1] = qm0 ? -1e10f : s[nf][1] * 0.125f * md0.y;
            s[nf][2] = qm1 ? -1e10f : s[nf][2] * 0.125f * md1.x;
            s[nf][3] = qm1 ? -1e10f : s[nf][3] * 0.125f * md1.y;
            mx0 = fmaxf(mx0, fmaxf(s[nf][0], s[nf][1]));
            mx1 = fmaxf(mx1, fmaxf(s[nf][2], s[nf][3]));
        }
        mx0 = fmaxf(mx0, __shfl_xor_sync(0xffffffffu, mx0, 1));
        mx0 = fmaxf(mx0, __shfl_xor_sync(0xffffffffu, mx0, 2));
        mx1 = fmaxf(mx1, __shfl_xor_sync(0xffffffffu, mx1, 1));
        mx1 = fmaxf(mx1, __shfl_xor_sync(0xffffffffu, mx1, 2));

        float mn0 = fmaxf(mr0, mx0), mn1 = fmaxf(mr1, mx1);
        float co0 = __expf(mr0 - mn0), co1 = __expf(mr1 - mn1);
        float rs0 = 0.f, rs1 = 0.f;
        #pragma unroll
        for (int nf = 0; nf < 8; ++nf) {
            float p0 = __expf(s[nf][0] - mn0);
            float p1 = __expf(s[nf][1] - mn0);
            float p2 = __expf(s[nf][2] - mn1);
            float p3 = __expf(s[nf][3] - mn1);
            rs0 += p0 + p1; rs1 += p2 + p3;
            *(__half2*)&Ps[r0 * 72 + nf * 8 + 2 * q]       = __floats2half2_rn(p0, p1);
            *(__half2*)&Ps[(r0 + 8) * 72 + nf * 8 + 2 * q] = __floats2half2_rn(p2, p3);
        }
        rs0 += __shfl_xor_sync(0xffffffffu, rs0, 1);
        rs0 += __shfl_xor_sync(0xffffffffu, rs0, 2);
        rs1 += __shfl_xor_sync(0xffffffffu, rs1, 1);
        rs1 += __shfl_xor_sync(0xffffffffu, rs1, 2);
        l0 = l0 * co0 + rs0;
        l1 = l1 * co1 + rs1;
        mr0 = mn0; mr1 = mn1;
        #pragma unroll
        for (int nf = 0; nf < 8; ++nf) {
            o[nf][0] *= co0; o[nf][1] *= co0;
            o[nf][2] *= co1; o[nf][3] *= co1;
        }
        __syncwarp();   // Ps rows of this warp written only by this warp

        // ---- O += P @ V ----
        #pragma unroll
        for (int kc = 0; kc < 4; ++kc) {
            unsigned a0, a1, a2, a3;
            ldsm4(a0, a1, a2, a3, &Ps[(w * 16 + rowA) * 72 + kc * 16 + colA]);
            #pragma unroll
            for (int nb = 0; nb < 4; ++nb) {
                unsigned b0, b1, b2, b3;
                ldsm4(b0, b1, b2, b3, &Vt[(nb * 16 + rowB) * 72 + kc * 16 + colB]);
                mma_f16(o[2 * nb][0], o[2 * nb][1], o[2 * nb][2], o[2 * nb][3],
                        a0, a1, a2, a3, b0, b1);
                mma_f16(o[2 * nb + 1][0], o[2 * nb + 1][1], o[2 * nb + 1][2],
                        o[2 * nb + 1][3], a0, a1, a2, a3, b2, b3);
            }
        }
    }

    // normalize, write [B,S,D] (tf32-rounded: feeds the output-projection GEMM)
    float i0 = 1.0f / l0, i1 = 1.0f / l1;
    float* ob = g_att + ((size_t)b * S + qt * 128) * D + h * 64;
    #pragma unroll
    for (int nf = 0; nf < 8; ++nf) {
        *(float2*)&ob[(size_t)r0 * D + nf * 8 + 2 * q] =
            make_float2(f2tff(o[nf][0] * i0), f2tff(o[nf][1] * i0));
        *(float2*)&ob[(size_t)(r0 + 8) * D + nf * 8 + 2 * q] =
            make_float2(f2tff(o[nf][2] * i1), f2tff(o[nf][3] * i1));
    }
}

// ---------------- launch ----------------
extern "C" void kernel_launch(void* const* d_in, const int* in_sizes, int n_in,
                              void* d_out, int out_size)
{
    const float* x   = (const float*)d_in[0];
    const void*  kpm = d_in[1];
    const float* mod = (const float*)d_in[2];
    const float* Wq  = (const float*)d_in[3];
    const float* bq  = (const float*)d_in[4];
    const float* Wk  = (const float*)d_in[5];
    const float* bk  = (const float*)d_in[6];
    const float* Wv  = (const float*)d_in[7];
    const float* bv  = (const float*)d_in[8];
    const float* Wo  = (const float*)d_in[9];
    const float* bo  = (const float*)d_in[10];
    float* out = (float*)d_out;

    void *qp, *kp, *vp;
    float *ap, *xr, *wr;
    cudaGetSymbolAddress(&qp, g_q);
    cudaGetSymbolAddress(&kp, g_k);
    cudaGetSymbolAddress(&vp, g_v);
    cudaGetSymbolAddress((void**)&ap, g_att);
    cudaGetSymbolAddress((void**)&xr, g_xr);
    cudaGetSymbolAddress((void**)&wr, g_wr);

    k_init_sig<<<1, 1>>>();
    k_detect<<<(B * S + 255) / 256, 256>>>((const unsigned char*)kpm);
    k_convert<<<(B * S + 255) / 256, 256>>>(kpm);

    // pre-round GEMM operands to tf32 (RNA) once
    const int n4x = M * D / 4, n4w = D * D / 4;
    k_round<<<(n4x + 255) / 256, 256>>>(x,  xr, n4x);
    k_round<<<(n4w + 255) / 256, 256>>>(Wq, wr + 0 * (size_t)D * D, n4w);
    k_round<<<(n4w + 255) / 256, 256>>>(Wk, wr + 1 * (size_t)D * D, n4w);
    k_round<<<(n4w + 255) / 256, 256>>>(Wv, wr + 2 * (size_t)D * D, n4w);
    k_round<<<(n4w + 255) / 256, 256>>>(Wo, wr + 3 * (size_t)D * D, n4w);

    constexpr int GSMEM = 3 * (128 * 20 + 16 * 136) * 4;  // 56832 B
    cudaFuncSetAttribute(k_gemm<0>, cudaFuncAttributeMaxDynamicSharedMemorySize, GSMEM);
    cudaFuncSetAttribute(k_gemm<1>, cudaFuncAttributeMaxDynamicSharedMemorySize, GSMEM);
    cudaFuncSetAttribute(k_gemm<2>, cudaFuncAttributeMaxDynamicSharedMemorySize, GSMEM);

    dim3 gg(D / 128, M / 128);
    k_gemm<1><<<gg, 256, GSMEM>>>(xr, wr + 0 * (size_t)D * D, bq, qp);
    k_gemm<1><<<gg, 256, GSMEM>>>(xr, wr + 1 * (size_t)D * D, bk, kp);
    k_gemm<2><<<gg, 256, GSMEM>>>(xr, wr + 2 * (size_t)D * D, bv, vp);

    constexpr int SMEM = (128 * 72 + 64 * 72 + 64 * 72 + 128 * 72) * 2;  // 55296 B
    cudaFuncSetAttribute(k_flash, cudaFuncAttributeMaxDynamicSharedMemorySize, SMEM);
    k_flash<<<dim3(H, B * (S / 128)), 256, SMEM>>>(mod);

    k_gemm<0><<<gg, 256, GSMEM>>>(ap, wr + 3 * (size_t)D * D, bo, out);
}